// round 1
// baseline (speedup 1.0000x reference)
#include <cuda_runtime.h>
#include <math.h>

#define Bv 2
#define Cv 4
#define Fv 512
#define Hv 8
#define Wv 1024
#define DHv 64
#define BCv (Bv*Cv)                 // 8
#define FWv (Fv*Wv)                 // 524288
#define BCFWv ((size_t)BCv*FWv)     // 4194304
#define QKELEMS ((size_t)BCv*Hv*Wv*Wv) // 67108864

// ---------------- scratch (device globals; no allocations allowed) ----------
__device__ __align__(256) float g_lin[3*BCFWv];   // post mc_linear, q/k/v
__device__ __align__(256) float g_proj[3*BCFWv];  // post conv(+rotary), q/k/v
__device__ __align__(256) float g_att[BCFWv];     // attention result in [b,c,f,w]

// ============================================================================
// Per-channel GEMM: Y[bc][g][w] = sum_f Wm[c][g][f] * X[bc][f][w]
// 128x128 tile, BK=8, 256 threads, 8x8 microtile.
// grid: (Wv/128, Fv/128, BCv)
// ============================================================================
__global__ __launch_bounds__(256)
void mc_gemm(const float* __restrict__ Wm, const float* __restrict__ X,
             float* __restrict__ Y)
{
    __shared__ __align__(16) float As[8][128];  // [k][m]
    __shared__ __align__(16) float Bs[8][128];  // [k][n]

    const int bc = blockIdx.z;
    const int c  = bc % Cv;
    const float* A  = Wm + (size_t)c * Fv * Fv;     // [512,512] row-major (g,f)
    const float* Bx = X  + (size_t)bc * FWv;        // [512,1024]
    float*       Cy = Y  + (size_t)bc * FWv;

    const int m0 = blockIdx.y * 128;
    const int n0 = blockIdx.x * 128;
    const int tid = threadIdx.x;
    const int tx = tid & 15;
    const int ty = tid >> 4;

    float acc[8][8];
#pragma unroll
    for (int i = 0; i < 8; i++)
#pragma unroll
        for (int j = 0; j < 8; j++) acc[i][j] = 0.f;

    const int a_row  = tid >> 1;          // 0..127
    const int a_col4 = (tid & 1) * 4;     // 0 or 4
    const int b_row  = tid >> 5;          // 0..7
    const int b_col4 = (tid & 31) * 4;    // 0..124

    for (int k0 = 0; k0 < Fv; k0 += 8) {
        float4 av = *(const float4*)(A  + (size_t)(m0 + a_row) * Fv + k0 + a_col4);
        float4 bv = *(const float4*)(Bx + (size_t)(k0 + b_row) * Wv + n0 + b_col4);
        As[a_col4 + 0][a_row] = av.x;
        As[a_col4 + 1][a_row] = av.y;
        As[a_col4 + 2][a_row] = av.z;
        As[a_col4 + 3][a_row] = av.w;
        *(float4*)&Bs[b_row][b_col4] = bv;
        __syncthreads();
#pragma unroll
        for (int kk = 0; kk < 8; kk++) {
            float af[8], bf[8];
            *(float4*)&af[0] = *(const float4*)&As[kk][ty * 8];
            *(float4*)&af[4] = *(const float4*)&As[kk][ty * 8 + 4];
            *(float4*)&bf[0] = *(const float4*)&Bs[kk][tx * 8];
            *(float4*)&bf[4] = *(const float4*)&Bs[kk][tx * 8 + 4];
#pragma unroll
            for (int i = 0; i < 8; i++)
#pragma unroll
                for (int j = 0; j < 8; j++)
                    acc[i][j] += af[i] * bf[j];
        }
        __syncthreads();
    }

#pragma unroll
    for (int i = 0; i < 8; i++) {
        const int g = m0 + ty * 8 + i;
        float* row = Cy + (size_t)g * Wv + n0 + tx * 8;
        *(float4*)(row)     = make_float4(acc[i][0], acc[i][1], acc[i][2], acc[i][3]);
        *(float4*)(row + 4) = make_float4(acc[i][4], acc[i][5], acc[i][6], acc[i][7]);
    }
}

// ============================================================================
// Channel-mixing conv (1xK, K=3, pad 1 along w) + bias, rotary fused for q/k.
// One thread handles one (p, b, f-pair, w): both f=2j and f=2j+1 for all 4
// output channels, so the rotary pair is in-register.
// total threads = 3 * Bv * (Fv/2) * Wv
// ============================================================================
__global__ __launch_bounds__(256)
void conv_rot(const float* __restrict__ wq, const float* __restrict__ bq,
              const float* __restrict__ wk, const float* __restrict__ bk,
              const float* __restrict__ wv, const float* __restrict__ bv)
{
    int t = blockIdx.x * blockDim.x + threadIdx.x;
    const int w  = t & (Wv - 1);
    int r = t >> 10;                       // (p, b, fpair)
    const int fp = r & (Fv / 2 - 1);       // 0..255
    r >>= 8;
    const int b = r & 1;
    const int p = r >> 1;                  // 0:q 1:k 2:v
    if (p > 2) return;

    const float* wc   = (p == 0) ? wq : (p == 1) ? wk : wv;
    const float* bias = (p == 0) ? bq : (p == 1) ? bk : bv;
    const float* lin  = g_lin  + (size_t)p * BCFWv + (size_t)b * Cv * FWv;
    float*       outp = g_proj + (size_t)p * BCFWv + (size_t)b * Cv * FWv;
    const int f0 = fp * 2;

    float xin[4][2][3];
#pragma unroll
    for (int i = 0; i < 4; i++) {
#pragma unroll
        for (int rr = 0; rr < 2; rr++) {
            const float* base = lin + (size_t)(i * Fv + f0 + rr) * Wv + w;
            xin[i][rr][0] = (w > 0)      ? base[-1] : 0.f;
            xin[i][rr][1] = base[0];
            xin[i][rr][2] = (w < Wv - 1) ? base[1]  : 0.f;
        }
    }

    float cw = 1.f, sw = 0.f;
    if (p < 2) {
        const int pi = fp & 31;  // pair index within head (DH=64 -> 32 pairs)
        // inv_freq = 10000^(-2*pi/64)
        const float inv = exp2f(-(float)(2 * pi) * (13.287712379549449f / 64.0f));
        sincosf((float)w * inv, &sw, &cw);
    }

#pragma unroll
    for (int o = 0; o < 4; o++) {
        float y0 = bias[o], y1 = bias[o];
#pragma unroll
        for (int i = 0; i < 4; i++) {
#pragma unroll
            for (int kk = 0; kk < 3; kk++) {
                const float wt = wc[(o * 4 + i) * 3 + kk];
                y0 += xin[i][0][kk] * wt;
                y1 += xin[i][1][kk] * wt;
            }
        }
        float o0 = y0, o1 = y1;
        if (p < 2) {           // rotary: even d: x*c - x_odd*s ; odd d: x*c + x_even*s
            o0 = y0 * cw - y1 * sw;
            o1 = y1 * cw + y0 * sw;
        }
        outp[(size_t)(o * Fv + f0)     * Wv + w] = o0;
        outp[(size_t)(o * Fv + f0 + 1) * Wv + w] = o1;
    }
}

// ============================================================================
// qk[bch][q][k] = (Q^T K)/sqrt(F) + prev + mask   (written into output buffer)
// 64x64 tile over (q,k), full K-dim = 64 (head dim). grid (16,16,64).
// ============================================================================
__global__ __launch_bounds__(256)
void qk_kernel(const float* __restrict__ prev, const float* __restrict__ mask,
               float* __restrict__ qk_out)
{
    __shared__ __align__(16) float Qs[64][68];
    __shared__ __align__(16) float Ks[64][68];

    const int bch = blockIdx.z;
    const int bc  = bch / Hv;
    const int h   = bch % Hv;
    const int q0  = blockIdx.y * 64;
    const int k0  = blockIdx.x * 64;
    const float* Qp = g_proj + (size_t)bc * FWv + (size_t)(h * DHv) * Wv;
    const float* Kp = g_proj + BCFWv + (size_t)bc * FWv + (size_t)(h * DHv) * Wv;

    const int tid = threadIdx.x;
    const int tx = tid & 15;
    const int ty = tid >> 4;

#pragma unroll
    for (int i = 0; i < 4; i++) {
        const int f4 = tid + i * 256;
        const int d  = f4 >> 4;
        const int c4 = (f4 & 15) << 2;
        *(float4*)&Qs[d][c4] = *(const float4*)(Qp + (size_t)d * Wv + q0 + c4);
        *(float4*)&Ks[d][c4] = *(const float4*)(Kp + (size_t)d * Wv + k0 + c4);
    }
    __syncthreads();

    float acc[4][4] = {};
#pragma unroll
    for (int d = 0; d < 64; d++) {
        float qf[4], kf[4];
        *(float4*)qf = *(const float4*)&Qs[d][ty * 4];
        *(float4*)kf = *(const float4*)&Ks[d][tx * 4];
#pragma unroll
        for (int i = 0; i < 4; i++)
#pragma unroll
            for (int j = 0; j < 4; j++)
                acc[i][j] += qf[i] * kf[j];
    }

    const float scale = 0.044194173824159216f;  // 1/sqrt(512)
    const size_t base = (size_t)bch * Wv * Wv;
#pragma unroll
    for (int i = 0; i < 4; i++) {
        const int q = q0 + ty * 4 + i;
        const size_t off = base + (size_t)q * Wv + k0 + tx * 4;
        float4 pv = *(const float4*)(prev + off);
        float4 mv = *(const float4*)(mask + (size_t)q * Wv + k0 + tx * 4);
        float4 res;
        res.x = acc[i][0] * scale + pv.x + mv.x;
        res.y = acc[i][1] * scale + pv.y + mv.y;
        res.z = acc[i][2] * scale + pv.z + mv.z;
        res.w = acc[i][3] * scale + pv.w + mv.w;
        *(float4*)(qk_out + off) = res;
    }
}

// ============================================================================
// softmax over k (row) + A = P @ V^T.  One block = (bch, 64 query rows).
// Stage 1: per-row max & sum(exp) via warp reductions.
// Stage 2: stream 64-wide k-tiles: P and V staged k-major in smem, 4x4 microtile.
// Writes g_att[bc][h*64+d][q] (the [b,c,f,w] layout the final GEMM wants).
// grid (16, 64)
// ============================================================================
__global__ __launch_bounds__(256)
void softmax_av(const float* __restrict__ qk)
{
    __shared__ __align__(16) float Ps[64][68];  // [k][q]
    __shared__ __align__(16) float Vs[64][68];  // [k][d]
    __shared__ float rmax[64], rinv[64];

    const int bch = blockIdx.y;
    const int bc  = bch / Hv;
    const int h   = bch % Hv;
    const int q0  = blockIdx.x * 64;
    const float* S  = qk + (size_t)bch * Wv * Wv + (size_t)q0 * Wv;  // [64][1024]
    const float* Vp = g_proj + 2 * BCFWv + (size_t)bc * FWv + (size_t)(h * DHv) * Wv;

    const int tid  = threadIdx.x;
    const int lane = tid & 31;
    const int wid  = tid >> 5;

    // ---- stage 1: row max + 1/sum(exp) ----
    for (int r = wid; r < 64; r += 8) {
        const float* row = S + (size_t)r * Wv;
        float m = -1e30f;
        for (int j = lane; j < Wv; j += 32) m = fmaxf(m, row[j]);
#pragma unroll
        for (int o = 16; o; o >>= 1) m = fmaxf(m, __shfl_xor_sync(0xffffffff, m, o));
        float s = 0.f;
        for (int j = lane; j < Wv; j += 32) s += __expf(row[j] - m);
#pragma unroll
        for (int o = 16; o; o >>= 1) s += __shfl_xor_sync(0xffffffff, s, o);
        if (lane == 0) { rmax[r] = m; rinv[r] = 1.f / s; }
    }
    __syncthreads();

    // ---- stage 2: A[q][d] = sum_k P[q][k] * V[d][k] ----
    const int tx = tid & 15;
    const int ty = tid >> 4;
    float acc[4][4] = {};

    for (int kt = 0; kt < Wv; kt += 64) {
#pragma unroll
        for (int i = 0; i < 4; i++) {
            const int f4 = tid + i * 256;
            const int r  = f4 >> 4;          // q-row for P, d-row for V
            const int c4 = (f4 & 15) << 2;   // k within tile
            float4 sv = *(const float4*)(S + (size_t)r * Wv + kt + c4);
            const float m = rmax[r], inv = rinv[r];
            Ps[c4 + 0][r] = __expf(sv.x - m) * inv;
            Ps[c4 + 1][r] = __expf(sv.y - m) * inv;
            Ps[c4 + 2][r] = __expf(sv.z - m) * inv;
            Ps[c4 + 3][r] = __expf(sv.w - m) * inv;
            float4 vv = *(const float4*)(Vp + (size_t)r * Wv + kt + c4);
            Vs[c4 + 0][r] = vv.x;
            Vs[c4 + 1][r] = vv.y;
            Vs[c4 + 2][r] = vv.z;
            Vs[c4 + 3][r] = vv.w;
        }
        __syncthreads();
#pragma unroll
        for (int kk = 0; kk < 64; kk++) {
            float pf[4], vf[4];
            *(float4*)pf = *(const float4*)&Ps[kk][ty * 4];
            *(float4*)vf = *(const float4*)&Vs[kk][tx * 4];
#pragma unroll
            for (int i = 0; i < 4; i++)
#pragma unroll
                for (int j = 0; j < 4; j++)
                    acc[i][j] += pf[i] * vf[j];
        }
        __syncthreads();
    }

    // write a[q][d] -> g_att[bc][h*64+d][q0+q]
    float* outp = g_att + (size_t)bc * FWv + (size_t)(h * DHv) * Wv + q0;
#pragma unroll
    for (int i = 0; i < 4; i++) {
        const int q = ty * 4 + i;
#pragma unroll
        for (int j = 0; j < 4; j++) {
            const int d = tx * 4 + j;
            outp[(size_t)d * Wv + q] = acc[i][j];
        }
    }
}

// ============================================================================
// launch
// ============================================================================
extern "C" void kernel_launch(void* const* d_in, const int* in_sizes, int n_in,
                              void* d_out, int out_size)
{
    (void)in_sizes; (void)n_in; (void)out_size;
    const float* x       = (const float*)d_in[0];
    const float* prev    = (const float*)d_in[1];
    const float* mask    = (const float*)d_in[2];
    const float* wq_lin  = (const float*)d_in[3];
    const float* wq_conv = (const float*)d_in[4];
    const float* bq      = (const float*)d_in[5];
    const float* wk_lin  = (const float*)d_in[6];
    const float* wk_conv = (const float*)d_in[7];
    const float* bk      = (const float*)d_in[8];
    const float* wv_lin  = (const float*)d_in[9];
    const float* wv_conv = (const float*)d_in[10];
    const float* bv      = (const float*)d_in[11];
    const float* wo_lin  = (const float*)d_in[12];

    float* out = (float*)d_out;            // [2,4,512,1024]
    float* qk  = out + BCFWv;              // [2,4,8,1024,1024]

    float* glin = nullptr;
    float* gatt = nullptr;
    cudaGetSymbolAddress((void**)&glin, g_lin);
    cudaGetSymbolAddress((void**)&gatt, g_att);

    const dim3 gemm_grid(Wv / 128, Fv / 128, BCv);

    // 1) per-channel linear projections
    mc_gemm<<<gemm_grid, 256>>>(wq_lin, x, glin);
    mc_gemm<<<gemm_grid, 256>>>(wk_lin, x, glin + BCFWv);
    mc_gemm<<<gemm_grid, 256>>>(wv_lin, x, glin + 2 * BCFWv);

    // 2) conv + bias (+ rotary for q,k)
    const int conv_threads = 3 * Bv * (Fv / 2) * Wv;
    conv_rot<<<conv_threads / 256, 256>>>(wq_conv, bq, wk_conv, bk, wv_conv, bv);

    // 3) scores -> qk output region
    qk_kernel<<<dim3(Wv / 64, Wv / 64, BCv * Hv), 256>>>(prev, mask, qk);

    // 4) softmax + P@V -> g_att ([b,c,f,w] layout)
    softmax_av<<<dim3(Wv / 64, BCv * Hv), 256>>>(qk);

    // 5) output projection -> out region
    mc_gemm<<<gemm_grid, 256>>>(wo_lin, gatt, out);
}

// round 5
// speedup vs baseline: 2.0381x; 2.0381x over previous
#include <cuda_runtime.h>
#include <cuda_bf16.h>
#include <math.h>
#include <cstdint>

#define Bv 2
#define Cv 4
#define Fv 512
#define Hv 8
#define Wv 1024
#define DHv 64
#define BCv (Bv*Cv)                 // 8
#define FWv (Fv*Wv)                 // 524288
#define BCFWv ((size_t)BCv*FWv)     // 4194304

typedef __nv_bfloat16 bf16;

// ---------------- scratch (device globals; no allocations allowed) ----------
__device__ __align__(256) float g_lin[3*BCFWv];        // post mc_linear q/k/v (fp32)
__device__ __align__(256) bf16 g_whi[4*(size_t)Cv*Fv*Fv];
__device__ __align__(256) bf16 g_wlo[4*(size_t)Cv*Fv*Fv];
__device__ __align__(256) bf16 g_xt_hi[BCFWv];         // x^T [bc][w][f]
__device__ __align__(256) bf16 g_xt_lo[BCFWv];
__device__ __align__(256) bf16 g_qb[BCFWv];            // q [bc][h][w][d] (single bf16)
__device__ __align__(256) bf16 g_kb[BCFWv];            // k [bc][h][w][d]
__device__ __align__(256) bf16 g_vb_hi[BCFWv];         // v [bc][f][w]
__device__ __align__(256) bf16 g_vb_lo[BCFWv];
__device__ __align__(256) bf16 g_at_hi[BCFWv];         // attn out [bc][w][f]
__device__ __align__(256) bf16 g_at_lo[BCFWv];

// ============================================================================
// mma.sync / ldmatrix helpers (baseline compute_103-safe)
// ============================================================================
__device__ __forceinline__ uint32_t smem_u32(const void* p) {
    uint32_t a;
    asm("{ .reg .u64 t; cvta.to.shared.u64 t, %1; cvt.u32.u64 %0, t; }" : "=r"(a) : "l"(p));
    return a;
}
__device__ __forceinline__ void ldsm4(uint32_t* r, uint32_t addr) {
    asm volatile("ldmatrix.sync.aligned.m8n8.x4.shared.b16 {%0,%1,%2,%3}, [%4];"
        : "=r"(r[0]), "=r"(r[1]), "=r"(r[2]), "=r"(r[3]) : "r"(addr));
}
__device__ __forceinline__ void mma16816(float* c, const uint32_t* a, const uint32_t* b) {
    asm volatile("mma.sync.aligned.m16n8k16.row.col.f32.bf16.bf16.f32 "
        "{%0,%1,%2,%3}, {%4,%5,%6,%7}, {%8,%9}, {%0,%1,%2,%3};"
        : "+f"(c[0]), "+f"(c[1]), "+f"(c[2]), "+f"(c[3])
        : "r"(a[0]), "r"(a[1]), "r"(a[2]), "r"(a[3]), "r"(b[0]), "r"(b[1]));
}
__device__ __forceinline__ void split_bf16(float v, bf16& h, bf16& l) {
    h = __float2bfloat16(v);
    l = __float2bfloat16(v - __bfloat162float(h));
}

// ============================================================================
// Conversion kernels
// ============================================================================
__global__ __launch_bounds__(256)
void cvt_weights(const float* __restrict__ w0, const float* __restrict__ w1,
                 const float* __restrict__ w2, const float* __restrict__ w3)
{
    size_t t = (size_t)blockIdx.x * 256 + threadIdx.x;   // 4 * 1M
    int m = (int)(t >> 20);
    const float* src = (m == 0) ? w0 : (m == 1) ? w1 : (m == 2) ? w2 : w3;
    float v = src[t & 1048575];
    bf16 h, l;
    split_bf16(v, h, l);
    g_whi[t] = h;
    g_wlo[t] = l;
}

__global__ __launch_bounds__(256)
void transpose_x(const float* __restrict__ x)
{
    __shared__ float tile[32][33];
    const int bc = blockIdx.z;
    const int w0 = blockIdx.x * 32, f0 = blockIdx.y * 32;
    const int tx = threadIdx.x & 31, ty = threadIdx.x >> 5;   // 32 x 8
    const float* src = x + (size_t)bc * FWv;
#pragma unroll
    for (int r = 0; r < 32; r += 8)
        tile[ty + r][tx] = src[(size_t)(f0 + ty + r) * Wv + w0 + tx];
    __syncthreads();
    bf16* hi = g_xt_hi + (size_t)bc * FWv;
    bf16* lo = g_xt_lo + (size_t)bc * FWv;
#pragma unroll
    for (int r = 0; r < 32; r += 8) {
        float v = tile[tx][ty + r];
        size_t idx = (size_t)(w0 + ty + r) * Fv + f0 + tx;
        bf16 h, l;
        split_bf16(v, h, l);
        hi[idx] = h;
        lo[idx] = l;
    }
}

// ============================================================================
// Per-channel GEMM via mma.sync, split hi/lo (3 products):
//   Y[bc][g][w] = sum_f W[c][g][f] * Xt[bc][w][f]
// Block 128x128, BK=32, 256 threads (8 warps, 2m x 4n, warp tile 64x32).
// grid: (Wv/128=8, Fv/128=4, BCv)
// ============================================================================
__global__ __launch_bounds__(256)
void mc_gemm_mma(const bf16* __restrict__ Whi, const bf16* __restrict__ Wlo,
                 const bf16* __restrict__ Xhi, const bf16* __restrict__ Xlo,
                 float* __restrict__ Y)
{
    __shared__ __align__(16) bf16 As[2][128][40];   // [hi/lo][m][k]
    __shared__ __align__(16) bf16 Bs[2][128][40];   // [hi/lo][n][k]

    const int tid = threadIdx.x, lane = tid & 31, wid = tid >> 5;
    const int wm = wid >> 2, wn = wid & 3;
    const int bc = blockIdx.z, c = bc & 3;
    const int m0 = blockIdx.y * 128, n0 = blockIdx.x * 128;

    const bf16* Ah = Whi + (size_t)c * Fv * Fv;
    const bf16* Al = Wlo + (size_t)c * Fv * Fv;
    const bf16* Bh = Xhi + (size_t)bc * FWv;
    const bf16* Bl = Xlo + (size_t)bc * FWv;
    float* Cy = Y + (size_t)bc * FWv;               // FIX (R3 bug): batch offset

    const int g_row = tid >> 2;            // 0..63 (x2 chunks -> 128 rows)
    const int g_kc  = (tid & 3) * 8;

    uint4 ra[2][2], rb[2][2];
    auto loadg = [&](int k0) {
#pragma unroll
        for (int t = 0; t < 2; t++) {
            const int row = g_row + t * 64;
            ra[0][t] = *(const uint4*)(Ah + (size_t)(m0 + row) * Fv + k0 + g_kc);
            ra[1][t] = *(const uint4*)(Al + (size_t)(m0 + row) * Fv + k0 + g_kc);
            rb[0][t] = *(const uint4*)(Bh + (size_t)(n0 + row) * Fv + k0 + g_kc);
            rb[1][t] = *(const uint4*)(Bl + (size_t)(n0 + row) * Fv + k0 + g_kc);
        }
    };

    float acc[4][4][4];
#pragma unroll
    for (int i = 0; i < 4; i++)
#pragma unroll
        for (int j = 0; j < 4; j++)
#pragma unroll
            for (int q = 0; q < 4; q++) acc[i][j][q] = 0.f;

    loadg(0);
    for (int it = 0; it < Fv / 32; it++) {
#pragma unroll
        for (int t = 0; t < 2; t++) {
            const int row = g_row + t * 64;
            *(uint4*)&As[0][row][g_kc] = ra[0][t];
            *(uint4*)&As[1][row][g_kc] = ra[1][t];
            *(uint4*)&Bs[0][row][g_kc] = rb[0][t];
            *(uint4*)&Bs[1][row][g_kc] = rb[1][t];
        }
        __syncthreads();
        if (it < Fv / 32 - 1) loadg((it + 1) * 32);

#pragma unroll
        for (int ks = 0; ks < 2; ks++) {
            uint32_t afh[4][4], afl[4][4], bfh[2][4], bfl[2][4];
            const int acol = ks * 16 + (lane >> 4) * 8;
            const int arow_l = lane & 15;
#pragma unroll
            for (int mf = 0; mf < 4; mf++) {
                const int r = wm * 64 + mf * 16 + arow_l;
                ldsm4(afh[mf], smem_u32(&As[0][r][acol]));
                ldsm4(afl[mf], smem_u32(&As[1][r][acol]));
            }
            const int brow_l = (lane & 7) + ((lane >> 4) & 1) * 8;
            const int bcol = ks * 16 + ((lane >> 3) & 1) * 8;
#pragma unroll
            for (int nh = 0; nh < 2; nh++) {
                const int r = wn * 32 + nh * 16 + brow_l;
                ldsm4(bfh[nh], smem_u32(&Bs[0][r][bcol]));
                ldsm4(bfl[nh], smem_u32(&Bs[1][r][bcol]));
            }
#pragma unroll
            for (int mf = 0; mf < 4; mf++)
#pragma unroll
                for (int nf = 0; nf < 4; nf++) {
                    const uint32_t* bh = &bfh[nf >> 1][(nf & 1) * 2];
                    const uint32_t* bl = &bfl[nf >> 1][(nf & 1) * 2];
                    mma16816(acc[mf][nf], afh[mf], bh);
                    mma16816(acc[mf][nf], afh[mf], bl);
                    mma16816(acc[mf][nf], afl[mf], bh);
                }
        }
        __syncthreads();
    }

#pragma unroll
    for (int mf = 0; mf < 4; mf++)
#pragma unroll
        for (int nf = 0; nf < 4; nf++) {
            const int r  = m0 + wm * 64 + mf * 16 + (lane >> 2);
            const int cc = n0 + wn * 32 + nf * 8 + (lane & 3) * 2;
            *(float2*)(Cy + (size_t)r * Wv + cc) =
                make_float2(acc[mf][nf][0], acc[mf][nf][1]);
            *(float2*)(Cy + (size_t)(r + 8) * Wv + cc) =
                make_float2(acc[mf][nf][2], acc[mf][nf][3]);
        }
}

// ============================================================================
// Channel-mixing conv (1x3, pad 1 along w) + bias + rotary for q/k.
// q,k -> bf16 [bc][h][w][d]; v -> bf16 hi/lo [bc][f][w].
// ============================================================================
__global__ __launch_bounds__(256)
void conv_rot(const float* __restrict__ wq, const float* __restrict__ bq,
              const float* __restrict__ wk, const float* __restrict__ bk,
              const float* __restrict__ wv, const float* __restrict__ bv)
{
    int t = blockIdx.x * blockDim.x + threadIdx.x;
    const int w = t & (Wv - 1);
    int r = t >> 10;
    const int fp = r & (Fv / 2 - 1);
    r >>= 8;
    const int b = r & 1;
    const int p = r >> 1;
    if (p > 2) return;

    const float* wc   = (p == 0) ? wq : (p == 1) ? wk : wv;
    const float* bias = (p == 0) ? bq : (p == 1) ? bk : bv;
    const float* lin  = g_lin + (size_t)p * BCFWv + (size_t)b * Cv * FWv;
    const int f0 = fp * 2;

    float xin[4][2][3];
#pragma unroll
    for (int i = 0; i < 4; i++)
#pragma unroll
        for (int rr = 0; rr < 2; rr++) {
            const float* base = lin + (size_t)(i * Fv + f0 + rr) * Wv + w;
            xin[i][rr][0] = (w > 0)      ? base[-1] : 0.f;
            xin[i][rr][1] = base[0];
            xin[i][rr][2] = (w < Wv - 1) ? base[1]  : 0.f;
        }

    float cw = 1.f, sw = 0.f;
    if (p < 2) {
        const int pi = fp & 31;
        const float inv = exp2f(-(float)(2 * pi) * (13.287712379549449f / 64.0f));
        sincosf((float)w * inv, &sw, &cw);
    }
    const int h  = f0 >> 6;
    const int d0 = f0 & 63;

#pragma unroll
    for (int o = 0; o < 4; o++) {
        float y0 = bias[o], y1 = bias[o];
#pragma unroll
        for (int i = 0; i < 4; i++)
#pragma unroll
            for (int kk = 0; kk < 3; kk++) {
                const float wt = wc[(o * 4 + i) * 3 + kk];
                y0 += xin[i][0][kk] * wt;
                y1 += xin[i][1][kk] * wt;
            }
        if (p < 2) {
            const float o0 = y0 * cw - y1 * sw;
            const float o1 = y1 * cw + y0 * sw;
            bf16* dst = (p == 0) ? g_qb : g_kb;
            const size_t idx = ((((size_t)(b * Cv + o) * Hv + h) * Wv) + w) * DHv + d0;
            dst[idx]     = __float2bfloat16(o0);
            dst[idx + 1] = __float2bfloat16(o1);
        } else {
            const size_t idx = ((size_t)(b * Cv + o) * Fv + f0) * Wv + w;
            bf16 h0, l0, h1, l1;
            split_bf16(y0, h0, l0);
            split_bf16(y1, h1, l1);
            g_vb_hi[idx] = h0; g_vb_lo[idx] = l0;
            g_vb_hi[idx + Wv] = h1; g_vb_lo[idx + Wv] = l1;
        }
    }
}

// ============================================================================
// qk = QK^T/sqrt(F) + prev + mask  via mma.sync (single bf16 Q,K).
// Block tile 128q x 128k, d = 64 fully resident. grid (8, 8, 64).
// ============================================================================
__global__ __launch_bounds__(256)
void qk_mma(const float* __restrict__ prev, const float* __restrict__ mask,
            float* __restrict__ qk_out)
{
    __shared__ __align__(16) bf16 Qs[128][72];
    __shared__ __align__(16) bf16 Ks[128][72];

    const int tid = threadIdx.x, lane = tid & 31, wid = tid >> 5;
    const int wm = wid >> 2, wn = wid & 3;
    const int bch = blockIdx.z;
    const int q0 = blockIdx.y * 128, k0 = blockIdx.x * 128;

    const bf16* Qp = g_qb + ((size_t)bch * Wv + q0) * DHv;
    const bf16* Kp = g_kb + ((size_t)bch * Wv + k0) * DHv;

#pragma unroll
    for (int t = 0; t < 4; t++) {
        const int idx = tid + t * 256;
        const int row = idx >> 3, dc = (idx & 7) * 8;
        *(uint4*)&Qs[row][dc] = *(const uint4*)(Qp + (size_t)row * DHv + dc);
        *(uint4*)&Ks[row][dc] = *(const uint4*)(Kp + (size_t)row * DHv + dc);
    }
    __syncthreads();

    float acc[4][4][4];
#pragma unroll
    for (int i = 0; i < 4; i++)
#pragma unroll
        for (int j = 0; j < 4; j++)
#pragma unroll
            for (int q = 0; q < 4; q++) acc[i][j][q] = 0.f;

#pragma unroll
    for (int ks = 0; ks < 4; ks++) {
        uint32_t af[4][4], bfr[2][4];
        const int acol = ks * 16 + (lane >> 4) * 8;
        const int arow_l = lane & 15;
#pragma unroll
        for (int mf = 0; mf < 4; mf++)
            ldsm4(af[mf], smem_u32(&Qs[wm * 64 + mf * 16 + arow_l][acol]));
        const int brow_l = (lane & 7) + ((lane >> 4) & 1) * 8;
        const int bcol = ks * 16 + ((lane >> 3) & 1) * 8;
#pragma unroll
        for (int nh = 0; nh < 2; nh++)
            ldsm4(bfr[nh], smem_u32(&Ks[wn * 32 + nh * 16 + brow_l][bcol]));
#pragma unroll
        for (int mf = 0; mf < 4; mf++)
#pragma unroll
            for (int nf = 0; nf < 4; nf++)
                mma16816(acc[mf][nf], af[mf], &bfr[nf >> 1][(nf & 1) * 2]);
    }

    const float scale = 0.044194173824159216f;   // 1/sqrt(512)
    const size_t base = (size_t)bch * Wv * Wv;
#pragma unroll
    for (int mf = 0; mf < 4; mf++)
#pragma unroll
        for (int nf = 0; nf < 4; nf++) {
            const int cc = k0 + wn * 32 + nf * 8 + (lane & 3) * 2;
#pragma unroll
            for (int hf = 0; hf < 2; hf++) {
                const int row = q0 + wm * 64 + mf * 16 + (lane >> 2) + hf * 8;
                const size_t off = base + (size_t)row * Wv + cc;
                float2 pv = *(const float2*)(prev + off);
                float2 mv = *(const float2*)(mask + (size_t)row * Wv + cc);
                float2 res;
                res.x = acc[mf][nf][hf * 2 + 0] * scale + pv.x + mv.x;
                res.y = acc[mf][nf][hf * 2 + 1] * scale + pv.y + mv.y;
                *(float2*)(qk_out + off) = res;
            }
        }
}

// ============================================================================
// Single-pass softmax + P@V via mma.sync (P hi/lo x V hi/lo, 3 products).
// No max subtraction (|S| small). Unnormalized exp accumulated; row sums
// tracked in-loop; scaled by 1/sum in epilogue. Output -> bf16 hi/lo [bc][w][f].
// Block: 128 q rows, warp grid 4m x 2n (warp tile 32q x 32d). grid (8, 64).
// ============================================================================
__global__ __launch_bounds__(256)
void softmax_av(const float* __restrict__ qk)
{
    __shared__ __align__(16) bf16 Ps[2][128][40];
    __shared__ __align__(16) bf16 Vs[2][64][40];
    __shared__ float rinv_s[128];

    const int tid = threadIdx.x, lane = tid & 31, wid = tid >> 5;
    const int wm = wid >> 1, wn = wid & 1;
    const int bch = blockIdx.y;
    const int bc = bch >> 3, h = bch & 7;
    const int q0 = blockIdx.x * 128;

    const float* S  = qk + (size_t)bch * Wv * Wv + (size_t)q0 * Wv;
    const bf16* Vh = g_vb_hi + ((size_t)bc * Fv + h * DHv) * Wv;
    const bf16* Vl = g_vb_lo + ((size_t)bc * Fv + h * DHv) * Wv;

    float acc[2][4][4];
#pragma unroll
    for (int i = 0; i < 2; i++)
#pragma unroll
        for (int j = 0; j < 4; j++)
#pragma unroll
            for (int q = 0; q < 4; q++) acc[i][j][q] = 0.f;
    float rsum[4] = {0.f, 0.f, 0.f, 0.f};

    const int p_row0 = tid >> 3;          // rows p_row0 + 32*i
    const int p_kc   = (tid & 7) * 4;
    const int v_row  = tid >> 2;          // 0..63
    const int v_kc   = (tid & 3) * 8;

    for (int kt = 0; kt < Wv; kt += 32) {
#pragma unroll
        for (int i = 0; i < 4; i++) {
            const int row = p_row0 + i * 32;
            float4 sv = *(const float4*)(S + (size_t)row * Wv + kt + p_kc);
            float p0 = __expf(sv.x), p1 = __expf(sv.y);
            float p2 = __expf(sv.z), p3 = __expf(sv.w);
            rsum[i] += (p0 + p1) + (p2 + p3);
            bf16 h0, l0, h1, l1, h2, l2, h3, l3;
            split_bf16(p0, h0, l0); split_bf16(p1, h1, l1);
            split_bf16(p2, h2, l2); split_bf16(p3, h3, l3);
            __nv_bfloat162 hv0 = {h0, h1}, hv1 = {h2, h3};
            __nv_bfloat162 lv0 = {l0, l1}, lv1 = {l2, l3};
            *(__nv_bfloat162*)&Ps[0][row][p_kc]     = hv0;
            *(__nv_bfloat162*)&Ps[0][row][p_kc + 2] = hv1;
            *(__nv_bfloat162*)&Ps[1][row][p_kc]     = lv0;
            *(__nv_bfloat162*)&Ps[1][row][p_kc + 2] = lv1;
        }
        *(uint4*)&Vs[0][v_row][v_kc] = *(const uint4*)(Vh + (size_t)v_row * Wv + kt + v_kc);
        *(uint4*)&Vs[1][v_row][v_kc] = *(const uint4*)(Vl + (size_t)v_row * Wv + kt + v_kc);
        __syncthreads();

#pragma unroll
        for (int ks = 0; ks < 2; ks++) {
            uint32_t ah[2][4], al[2][4], bh[2][4], bl[2][4];
            const int acol = ks * 16 + (lane >> 4) * 8;
            const int arow_l = lane & 15;
#pragma unroll
            for (int mf = 0; mf < 2; mf++) {
                const int r = wm * 32 + mf * 16 + arow_l;
                ldsm4(ah[mf], smem_u32(&Ps[0][r][acol]));
                ldsm4(al[mf], smem_u32(&Ps[1][r][acol]));
            }
            const int brow_l = (lane & 7) + ((lane >> 4) & 1) * 8;
            const int bcol = ks * 16 + ((lane >> 3) & 1) * 8;
#pragma unroll
            for (int nh = 0; nh < 2; nh++) {
                const int r = wn * 32 + nh * 16 + brow_l;
                ldsm4(bh[nh], smem_u32(&Vs[0][r][bcol]));
                ldsm4(bl[nh], smem_u32(&Vs[1][r][bcol]));
            }
#pragma unroll
            for (int mf = 0; mf < 2; mf++)
#pragma unroll
                for (int nf = 0; nf < 4; nf++) {
                    const uint32_t* bph = &bh[nf >> 1][(nf & 1) * 2];
                    const uint32_t* bpl = &bl[nf >> 1][(nf & 1) * 2];
                    mma16816(acc[mf][nf], ah[mf], bph);
                    mma16816(acc[mf][nf], ah[mf], bpl);
                    mma16816(acc[mf][nf], al[mf], bph);
                }
        }
        __syncthreads();
    }

    // reduce row sums across the 8 threads sharing each row (consecutive tids)
#pragma unroll
    for (int i = 0; i < 4; i++) {
        float s = rsum[i];
        s += __shfl_xor_sync(0xffffffff, s, 1);
        s += __shfl_xor_sync(0xffffffff, s, 2);
        s += __shfl_xor_sync(0xffffffff, s, 4);
        if ((lane & 7) == 0) rinv_s[p_row0 + i * 32] = 1.f / s;
    }
    __syncthreads();

    // epilogue: scale by rinv, write bf16 hi/lo transposed [bc][w][f]
    bf16* hi = g_at_hi + (size_t)bc * FWv;
    bf16* lo = g_at_lo + (size_t)bc * FWv;
#pragma unroll
    for (int mf = 0; mf < 2; mf++)
#pragma unroll
        for (int nf = 0; nf < 4; nf++) {
            const int d = wn * 32 + nf * 8 + (lane & 3) * 2;
#pragma unroll
            for (int hf = 0; hf < 2; hf++) {
                const int ql = wm * 32 + mf * 16 + (lane >> 2) + hf * 8;
                const float inv = rinv_s[ql];
                const float v0 = acc[mf][nf][hf * 2 + 0] * inv;
                const float v1 = acc[mf][nf][hf * 2 + 1] * inv;
                bf16 h0, l0, h1, l1;
                split_bf16(v0, h0, l0);
                split_bf16(v1, h1, l1);
                const size_t idx = (size_t)(q0 + ql) * Fv + h * DHv + d;
                *(__nv_bfloat162*)(hi + idx) = __nv_bfloat162{h0, h1};
                *(__nv_bfloat162*)(lo + idx) = __nv_bfloat162{l0, l1};
            }
        }
}

// ============================================================================
// launch
// ============================================================================
extern "C" void kernel_launch(void* const* d_in, const int* in_sizes, int n_in,
                              void* d_out, int out_size)
{
    (void)in_sizes; (void)n_in; (void)out_size;
    const float* x       = (const float*)d_in[0];
    const float* prev    = (const float*)d_in[1];
    const float* mask    = (const float*)d_in[2];
    const float* wq_lin  = (const float*)d_in[3];
    const float* wq_conv = (const float*)d_in[4];
    const float* bq      = (const float*)d_in[5];
    const float* wk_lin  = (const float*)d_in[6];
    const float* wk_conv = (const float*)d_in[7];
    const float* bk      = (const float*)d_in[8];
    const float* wv_lin  = (const float*)d_in[9];
    const float* wv_conv = (const float*)d_in[10];
    const float* bv      = (const float*)d_in[11];
    const float* wo_lin  = (const float*)d_in[12];

    float* out = (float*)d_out;            // [2,4,512,1024]
    float* qk  = out + BCFWv;              // [2,4,8,1024,1024]

    float* glin = nullptr;
    bf16 *whi = nullptr, *wlo = nullptr, *xhi = nullptr, *xlo = nullptr;
    bf16 *ahi = nullptr, *alo = nullptr;
    cudaGetSymbolAddress((void**)&glin, g_lin);
    cudaGetSymbolAddress((void**)&whi, g_whi);
    cudaGetSymbolAddress((void**)&wlo, g_wlo);
    cudaGetSymbolAddress((void**)&xhi, g_xt_hi);
    cudaGetSymbolAddress((void**)&xlo, g_xt_lo);
    cudaGetSymbolAddress((void**)&ahi, g_at_hi);
    cudaGetSymbolAddress((void**)&alo, g_at_lo);

    const size_t WSZ = (size_t)Cv * Fv * Fv;   // 1M per weight set

    // 0) conversions
    cvt_weights<<<(4 * 1048576) / 256, 256>>>(wq_lin, wk_lin, wv_lin, wo_lin);
    transpose_x<<<dim3(Wv / 32, Fv / 32, BCv), 256>>>(x);

    // 1) per-channel linear projections (HMMA)
    const dim3 gg(Wv / 128, Fv / 128, BCv);
    mc_gemm_mma<<<gg, 256>>>(whi + 0 * WSZ, wlo + 0 * WSZ, xhi, xlo, glin);
    mc_gemm_mma<<<gg, 256>>>(whi + 1 * WSZ, wlo + 1 * WSZ, xhi, xlo, glin + BCFWv);
    mc_gemm_mma<<<gg, 256>>>(whi + 2 * WSZ, wlo + 2 * WSZ, xhi, xlo, glin + 2 * BCFWv);

    // 2) conv + bias + rotary -> bf16 q,k,v
    const int conv_threads = 3 * Bv * (Fv / 2) * Wv;
    conv_rot<<<conv_threads / 256, 256>>>(wq_conv, bq, wk_conv, bk, wv_conv, bv);

    // 3) scores (HMMA) -> qk output region
    qk_mma<<<dim3(Wv / 128, Wv / 128, BCv * Hv), 256>>>(prev, mask, qk);

    // 4) single-pass softmax + P@V (HMMA) -> bf16 hi/lo [bc][w][f]
    softmax_av<<<dim3(Wv / 128, BCv * Hv), 256>>>(qk);

    // 5) output projection (HMMA)
    mc_gemm_mma<<<gg, 256>>>(whi + 3 * WSZ, wlo + 3 * WSZ, ahi, alo, out);
}

// round 6
// speedup vs baseline: 2.1845x; 1.0718x over previous
#include <cuda_runtime.h>
#include <cuda_bf16.h>
#include <math.h>
#include <cstdint>

#define Bv 2
#define Cv 4
#define Fv 512
#define Hv 8
#define Wv 1024
#define DHv 64
#define BCv (Bv*Cv)                 // 8
#define FWv (Fv*Wv)                 // 524288
#define BCFWv ((size_t)BCv*FWv)     // 4194304

typedef __nv_bfloat16 bf16;

// ---------------- scratch (device globals; no allocations allowed) ----------
__device__ __align__(256) float g_lin[3*BCFWv];        // post mc_linear q/k/v (fp32)
__device__ __align__(256) bf16 g_whi[4*(size_t)Cv*Fv*Fv];
__device__ __align__(256) bf16 g_wlo[4*(size_t)Cv*Fv*Fv];
__device__ __align__(256) bf16 g_xt_hi[BCFWv];         // x^T [bc][w][f]
__device__ __align__(256) bf16 g_xt_lo[BCFWv];
__device__ __align__(256) bf16 g_qb[BCFWv];            // q [bc][h][w][d] (single bf16)
__device__ __align__(256) bf16 g_kb[BCFWv];            // k [bc][h][w][d]
__device__ __align__(256) bf16 g_vb_hi[BCFWv];         // v [bc][f][w]
__device__ __align__(256) bf16 g_vb_lo[BCFWv];
__device__ __align__(256) bf16 g_at_hi[BCFWv];         // attn out [bc][w][f]
__device__ __align__(256) bf16 g_at_lo[BCFWv];

// ============================================================================
// mma.sync / ldmatrix helpers
// ============================================================================
__device__ __forceinline__ uint32_t smem_u32(const void* p) {
    uint32_t a;
    asm("{ .reg .u64 t; cvta.to.shared.u64 t, %1; cvt.u32.u64 %0, t; }" : "=r"(a) : "l"(p));
    return a;
}
__device__ __forceinline__ void ldsm4(uint32_t* r, uint32_t addr) {
    asm volatile("ldmatrix.sync.aligned.m8n8.x4.shared.b16 {%0,%1,%2,%3}, [%4];"
        : "=r"(r[0]), "=r"(r[1]), "=r"(r[2]), "=r"(r[3]) : "r"(addr));
}
__device__ __forceinline__ void mma16816(float* c, const uint32_t* a, const uint32_t* b) {
    asm volatile("mma.sync.aligned.m16n8k16.row.col.f32.bf16.bf16.f32 "
        "{%0,%1,%2,%3}, {%4,%5,%6,%7}, {%8,%9}, {%0,%1,%2,%3};"
        : "+f"(c[0]), "+f"(c[1]), "+f"(c[2]), "+f"(c[3])
        : "r"(a[0]), "r"(a[1]), "r"(a[2]), "r"(a[3]), "r"(b[0]), "r"(b[1]));
}
__device__ __forceinline__ void split_bf16(float v, bf16& h, bf16& l) {
    h = __float2bfloat16(v);
    l = __float2bfloat16(v - __bfloat162float(h));
}
// split two floats into packed bf16x2 hi and lo words
__device__ __forceinline__ void pack2(float a, float b, uint32_t& hi, uint32_t& lo) {
    bf16 ha, la, hb, lb;
    split_bf16(a, ha, la);
    split_bf16(b, hb, lb);
    __nv_bfloat162 th{ha, hb}, tl{la, lb};
    hi = *(uint32_t*)&th;
    lo = *(uint32_t*)&tl;
}

// ============================================================================
// Conversion kernels
// ============================================================================
__global__ __launch_bounds__(256)
void cvt_weights(const float* __restrict__ w0, const float* __restrict__ w1,
                 const float* __restrict__ w2, const float* __restrict__ w3)
{
    size_t t = (size_t)blockIdx.x * 256 + threadIdx.x;   // 4 * 1M
    int m = (int)(t >> 20);
    const float* src = (m == 0) ? w0 : (m == 1) ? w1 : (m == 2) ? w2 : w3;
    float v = src[t & 1048575];
    bf16 h, l;
    split_bf16(v, h, l);
    g_whi[t] = h;
    g_wlo[t] = l;
}

__global__ __launch_bounds__(256)
void transpose_x(const float* __restrict__ x)
{
    __shared__ float tile[32][33];
    const int bc = blockIdx.z;
    const int w0 = blockIdx.x * 32, f0 = blockIdx.y * 32;
    const int tx = threadIdx.x & 31, ty = threadIdx.x >> 5;   // 32 x 8
    const float* src = x + (size_t)bc * FWv;
#pragma unroll
    for (int r = 0; r < 32; r += 8)
        tile[ty + r][tx] = src[(size_t)(f0 + ty + r) * Wv + w0 + tx];
    __syncthreads();
    bf16* hi = g_xt_hi + (size_t)bc * FWv;
    bf16* lo = g_xt_lo + (size_t)bc * FWv;
#pragma unroll
    for (int r = 0; r < 32; r += 8) {
        float v = tile[tx][ty + r];
        size_t idx = (size_t)(w0 + ty + r) * Fv + f0 + tx;
        bf16 h, l;
        split_bf16(v, h, l);
        hi[idx] = h;
        lo[idx] = l;
    }
}

// ============================================================================
// Per-channel GEMM via mma.sync, split hi/lo (3 products).
// grid z = nsets*8: s = z>>3 selects weight set (+ output slab), bc = z&7.
// ============================================================================
__global__ __launch_bounds__(256)
void mc_gemm_mma(const bf16* __restrict__ Whi, const bf16* __restrict__ Wlo,
                 const bf16* __restrict__ Xhi, const bf16* __restrict__ Xlo,
                 float* __restrict__ Y)
{
    __shared__ __align__(16) bf16 As[2][128][40];   // [hi/lo][m][k]
    __shared__ __align__(16) bf16 Bs[2][128][40];   // [hi/lo][n][k]

    const int tid = threadIdx.x, lane = tid & 31, wid = tid >> 5;
    const int wm = wid >> 2, wn = wid & 3;
    const int s = blockIdx.z >> 3, bc = blockIdx.z & 7, c = bc & 3;
    const int m0 = blockIdx.y * 128, n0 = blockIdx.x * 128;

    const bf16* Ah = Whi + ((size_t)s * Cv + c) * Fv * Fv;
    const bf16* Al = Wlo + ((size_t)s * Cv + c) * Fv * Fv;
    const bf16* Bh = Xhi + (size_t)bc * FWv;
    const bf16* Bl = Xlo + (size_t)bc * FWv;
    float* Cy = Y + ((size_t)s * BCv + bc) * FWv;

    const int g_row = tid >> 2;            // 0..63 (x2 chunks -> 128 rows)
    const int g_kc  = (tid & 3) * 8;

    uint4 ra[2][2], rb[2][2];
    auto loadg = [&](int k0) {
#pragma unroll
        for (int t = 0; t < 2; t++) {
            const int row = g_row + t * 64;
            ra[0][t] = *(const uint4*)(Ah + (size_t)(m0 + row) * Fv + k0 + g_kc);
            ra[1][t] = *(const uint4*)(Al + (size_t)(m0 + row) * Fv + k0 + g_kc);
            rb[0][t] = *(const uint4*)(Bh + (size_t)(n0 + row) * Fv + k0 + g_kc);
            rb[1][t] = *(const uint4*)(Bl + (size_t)(n0 + row) * Fv + k0 + g_kc);
        }
    };

    float acc[4][4][4];
#pragma unroll
    for (int i = 0; i < 4; i++)
#pragma unroll
        for (int j = 0; j < 4; j++)
#pragma unroll
            for (int q = 0; q < 4; q++) acc[i][j][q] = 0.f;

    loadg(0);
    for (int it = 0; it < Fv / 32; it++) {
#pragma unroll
        for (int t = 0; t < 2; t++) {
            const int row = g_row + t * 64;
            *(uint4*)&As[0][row][g_kc] = ra[0][t];
            *(uint4*)&As[1][row][g_kc] = ra[1][t];
            *(uint4*)&Bs[0][row][g_kc] = rb[0][t];
            *(uint4*)&Bs[1][row][g_kc] = rb[1][t];
        }
        __syncthreads();
        if (it < Fv / 32 - 1) loadg((it + 1) * 32);

#pragma unroll
        for (int ks = 0; ks < 2; ks++) {
            uint32_t afh[4][4], afl[4][4], bfh[2][4], bfl[2][4];
            const int acol = ks * 16 + (lane >> 4) * 8;
            const int arow_l = lane & 15;
#pragma unroll
            for (int mf = 0; mf < 4; mf++) {
                const int r = wm * 64 + mf * 16 + arow_l;
                ldsm4(afh[mf], smem_u32(&As[0][r][acol]));
                ldsm4(afl[mf], smem_u32(&As[1][r][acol]));
            }
            const int brow_l = (lane & 7) + ((lane >> 4) & 1) * 8;
            const int bcol = ks * 16 + ((lane >> 3) & 1) * 8;
#pragma unroll
            for (int nh = 0; nh < 2; nh++) {
                const int r = wn * 32 + nh * 16 + brow_l;
                ldsm4(bfh[nh], smem_u32(&Bs[0][r][bcol]));
                ldsm4(bfl[nh], smem_u32(&Bs[1][r][bcol]));
            }
#pragma unroll
            for (int mf = 0; mf < 4; mf++)
#pragma unroll
                for (int nf = 0; nf < 4; nf++) {
                    const uint32_t* bh = &bfh[nf >> 1][(nf & 1) * 2];
                    const uint32_t* bl = &bfl[nf >> 1][(nf & 1) * 2];
                    mma16816(acc[mf][nf], afh[mf], bh);
                    mma16816(acc[mf][nf], afh[mf], bl);
                    mma16816(acc[mf][nf], afl[mf], bh);
                }
        }
        __syncthreads();
    }

#pragma unroll
    for (int mf = 0; mf < 4; mf++)
#pragma unroll
        for (int nf = 0; nf < 4; nf++) {
            const int r  = m0 + wm * 64 + mf * 16 + (lane >> 2);
            const int cc = n0 + wn * 32 + nf * 8 + (lane & 3) * 2;
            *(float2*)(Cy + (size_t)r * Wv + cc) =
                make_float2(acc[mf][nf][0], acc[mf][nf][1]);
            *(float2*)(Cy + (size_t)(r + 8) * Wv + cc) =
                make_float2(acc[mf][nf][2], acc[mf][nf][3]);
        }
}

// ============================================================================
// Channel-mixing conv (1x3, pad 1 along w) + bias + rotary for q/k.
// q,k -> bf16 [bc][h][w][d]; v -> bf16 hi/lo [bc][f][w].
// ============================================================================
__global__ __launch_bounds__(256)
void conv_rot(const float* __restrict__ wq, const float* __restrict__ bq,
              const float* __restrict__ wk, const float* __restrict__ bk,
              const float* __restrict__ wv, const float* __restrict__ bv)
{
    int t = blockIdx.x * blockDim.x + threadIdx.x;
    const int w = t & (Wv - 1);
    int r = t >> 10;
    const int fp = r & (Fv / 2 - 1);
    r >>= 8;
    const int b = r & 1;
    const int p = r >> 1;
    if (p > 2) return;

    const float* wc   = (p == 0) ? wq : (p == 1) ? wk : wv;
    const float* bias = (p == 0) ? bq : (p == 1) ? bk : bv;
    const float* lin  = g_lin + (size_t)p * BCFWv + (size_t)b * Cv * FWv;
    const int f0 = fp * 2;

    float xin[4][2][3];
#pragma unroll
    for (int i = 0; i < 4; i++)
#pragma unroll
        for (int rr = 0; rr < 2; rr++) {
            const float* base = lin + (size_t)(i * Fv + f0 + rr) * Wv + w;
            xin[i][rr][0] = (w > 0)      ? base[-1] : 0.f;
            xin[i][rr][1] = base[0];
            xin[i][rr][2] = (w < Wv - 1) ? base[1]  : 0.f;
        }

    float cw = 1.f, sw = 0.f;
    if (p < 2) {
        const int pi = fp & 31;
        const float inv = exp2f(-(float)(2 * pi) * (13.287712379549449f / 64.0f));
        sincosf((float)w * inv, &sw, &cw);
    }
    const int h  = f0 >> 6;
    const int d0 = f0 & 63;

#pragma unroll
    for (int o = 0; o < 4; o++) {
        float y0 = bias[o], y1 = bias[o];
#pragma unroll
        for (int i = 0; i < 4; i++)
#pragma unroll
            for (int kk = 0; kk < 3; kk++) {
                const float wt = wc[(o * 4 + i) * 3 + kk];
                y0 += xin[i][0][kk] * wt;
                y1 += xin[i][1][kk] * wt;
            }
        if (p < 2) {
            const float o0 = y0 * cw - y1 * sw;
            const float o1 = y1 * cw + y0 * sw;
            bf16* dst = (p == 0) ? g_qb : g_kb;
            const size_t idx = ((((size_t)(b * Cv + o) * Hv + h) * Wv) + w) * DHv + d0;
            dst[idx]     = __float2bfloat16(o0);
            dst[idx + 1] = __float2bfloat16(o1);
        } else {
            const size_t idx = ((size_t)(b * Cv + o) * Fv + f0) * Wv + w;
            bf16 h0, l0, h1, l1;
            split_bf16(y0, h0, l0);
            split_bf16(y1, h1, l1);
            g_vb_hi[idx] = h0; g_vb_lo[idx] = l0;
            g_vb_hi[idx + Wv] = h1; g_vb_lo[idx + Wv] = l1;
        }
    }
}

// ============================================================================
// FUSED attention: S = QK^T/sqrt(F)+prev+mask (-> qk_out), P = exp(S) kept in
// registers (C-fragment of S == A-fragment of P@V), O = P@V normalized by
// in-register row sums. One block = 128 q rows x full k. 8 warps, 16 q rows
// each. K-chunk 64. P hi/lo x V hi/lo (3 products). grid (8, 64).
// ============================================================================
__global__ __launch_bounds__(256)
void attn_fused(const float* __restrict__ prev, const float* __restrict__ mask,
                float* __restrict__ qk_out)
{
    __shared__ __align__(16) bf16 Qs[128][72];
    __shared__ __align__(16) bf16 Ks[64][72];
    __shared__ __align__(16) bf16 Vhs[64][72];
    __shared__ __align__(16) bf16 Vls[64][72];

    const int tid = threadIdx.x, lane = tid & 31, wid = tid >> 5;
    const int bch = blockIdx.y;
    const int bc = bch >> 3, h = bch & 7;
    const int q0 = blockIdx.x * 128;

    const bf16* Qp = g_qb + ((size_t)bch * Wv + q0) * DHv;
    const bf16* Kp = g_kb + (size_t)bch * Wv * DHv;
    const bf16* Vh = g_vb_hi + ((size_t)bc * Fv + h * DHv) * Wv;
    const bf16* Vl = g_vb_lo + ((size_t)bc * Fv + h * DHv) * Wv;
    const size_t sbase = (size_t)bch * Wv * Wv;

    // load Q tile 128x64
#pragma unroll
    for (int t = 0; t < 4; t++) {
        const int idx = tid + t * 256;
        const int row = idx >> 3, dc = (idx & 7) * 8;
        *(uint4*)&Qs[row][dc] = *(const uint4*)(Qp + (size_t)row * DHv + dc);
    }
    __syncthreads();

    // per-warp Q fragments (m16 x k64), chunk-invariant
    uint32_t qf[4][4];
#pragma unroll
    for (int ks = 0; ks < 4; ks++)
        ldsm4(qf[ks], smem_u32(&Qs[wid * 16 + (lane & 15)][ks * 16 + (lane >> 4) * 8]));

    float accO[8][4];
#pragma unroll
    for (int i = 0; i < 8; i++)
#pragma unroll
        for (int q = 0; q < 4; q++) accO[i][q] = 0.f;
    float rs0 = 0.f, rs1 = 0.f;

    const int r0 = lane >> 2;           // row within m16 (and +8)
    const int c0 = (lane & 3) * 2;      // col pair within n8
    const int qrow = q0 + wid * 16 + r0;
    const float scale = 0.044194173824159216f;   // 1/sqrt(512)
    const int brow = (lane & 7) + ((lane >> 4) & 1) * 8;
    const int bsel = ((lane >> 3) & 1) * 8;

    for (int kt = 0; kt < Wv; kt += 64) {
        // cooperative load K, Vhi, Vlo chunks (64x64 each)
        __syncthreads();
#pragma unroll
        for (int t = 0; t < 2; t++) {
            const int idx = tid + t * 256;
            const int row = idx >> 3, dc = (idx & 7) * 8;
            *(uint4*)&Ks[row][dc]  = *(const uint4*)(Kp + (size_t)(kt + row) * DHv + dc);
            *(uint4*)&Vhs[row][dc] = *(const uint4*)(Vh + (size_t)row * Wv + kt + dc);
            *(uint4*)&Vls[row][dc] = *(const uint4*)(Vl + (size_t)row * Wv + kt + dc);
        }
        __syncthreads();

        // ---- S = Q K^T (m16 x n64 per warp) ----
        float accS[8][4];
#pragma unroll
        for (int i = 0; i < 8; i++)
#pragma unroll
            for (int q = 0; q < 4; q++) accS[i][q] = 0.f;
#pragma unroll
        for (int ks = 0; ks < 4; ks++) {
            uint32_t kf[4][4];
#pragma unroll
            for (int np = 0; np < 4; np++)
                ldsm4(kf[np], smem_u32(&Ks[np * 16 + brow][ks * 16 + bsel]));
#pragma unroll
            for (int np = 0; np < 4; np++) {
                mma16816(accS[2 * np],     qf[ks], &kf[np][0]);
                mma16816(accS[2 * np + 1], qf[ks], &kf[np][2]);
            }
        }

        // ---- epilogue: +prev+mask, write qk, exp -> P fragments ----
        uint32_t Phi[4][4], Plo[4][4];
#pragma unroll
        for (int j = 0; j < 8; j++) {
            const int kk = kt + j * 8 + c0;
            const size_t off0 = sbase + (size_t)qrow * Wv + kk;
            const float2 pv0 = *(const float2*)(prev + off0);
            const float2 pv1 = *(const float2*)(prev + off0 + 8 * Wv);
            const float2 mv0 = *(const float2*)(mask + (size_t)qrow * Wv + kk);
            const float2 mv1 = *(const float2*)(mask + (size_t)(qrow + 8) * Wv + kk);
            const float s00 = accS[j][0] * scale + pv0.x + mv0.x;
            const float s01 = accS[j][1] * scale + pv0.y + mv0.y;
            const float s10 = accS[j][2] * scale + pv1.x + mv1.x;
            const float s11 = accS[j][3] * scale + pv1.y + mv1.y;
            *(float2*)(qk_out + off0)          = make_float2(s00, s01);
            *(float2*)(qk_out + off0 + 8 * Wv) = make_float2(s10, s11);
            const float p00 = __expf(s00), p01 = __expf(s01);
            const float p10 = __expf(s10), p11 = __expf(s11);
            rs0 += p00 + p01;
            rs1 += p10 + p11;
            pack2(p00, p01, Phi[j >> 1][(j & 1) * 2],     Plo[j >> 1][(j & 1) * 2]);
            pack2(p10, p11, Phi[j >> 1][(j & 1) * 2 + 1], Plo[j >> 1][(j & 1) * 2 + 1]);
        }

        // ---- O += P V^T (3 products) ----
#pragma unroll
        for (int kp = 0; kp < 4; kp++) {
            uint32_t vh[4][4], vl[4][4];
#pragma unroll
            for (int dp = 0; dp < 4; dp++) {
                ldsm4(vh[dp], smem_u32(&Vhs[dp * 16 + brow][kp * 16 + bsel]));
                ldsm4(vl[dp], smem_u32(&Vls[dp * 16 + brow][kp * 16 + bsel]));
            }
#pragma unroll
            for (int dp = 0; dp < 4; dp++) {
                mma16816(accO[2 * dp],     Phi[kp], &vh[dp][0]);
                mma16816(accO[2 * dp + 1], Phi[kp], &vh[dp][2]);
                mma16816(accO[2 * dp],     Phi[kp], &vl[dp][0]);
                mma16816(accO[2 * dp + 1], Phi[kp], &vl[dp][2]);
                mma16816(accO[2 * dp],     Plo[kp], &vh[dp][0]);
                mma16816(accO[2 * dp + 1], Plo[kp], &vh[dp][2]);
            }
        }
    }

    // row sums: reduce over the 4 lanes sharing each row
    rs0 += __shfl_xor_sync(0xffffffff, rs0, 1);
    rs0 += __shfl_xor_sync(0xffffffff, rs0, 2);
    rs1 += __shfl_xor_sync(0xffffffff, rs1, 1);
    rs1 += __shfl_xor_sync(0xffffffff, rs1, 2);
    const float inv0 = 1.f / rs0, inv1 = 1.f / rs1;

    // write O normalized -> g_at hi/lo [bc][w=q][f=h*64+d]
    bf16* hi = g_at_hi + (size_t)bc * FWv;
    bf16* lo = g_at_lo + (size_t)bc * FWv;
    const size_t row0 = (size_t)qrow * Fv + h * DHv;
#pragma unroll
    for (int j = 0; j < 8; j++) {
        const int d = j * 8 + c0;
        uint32_t ph, pl;
        pack2(accO[j][0] * inv0, accO[j][1] * inv0, ph, pl);
        *(uint32_t*)(hi + row0 + d) = ph;
        *(uint32_t*)(lo + row0 + d) = pl;
        pack2(accO[j][2] * inv1, accO[j][3] * inv1, ph, pl);
        *(uint32_t*)(hi + row0 + 8 * Fv + d) = ph;
        *(uint32_t*)(lo + row0 + 8 * Fv + d) = pl;
    }
}

// ============================================================================
// launch
// ============================================================================
extern "C" void kernel_launch(void* const* d_in, const int* in_sizes, int n_in,
                              void* d_out, int out_size)
{
    (void)in_sizes; (void)n_in; (void)out_size;
    const float* x       = (const float*)d_in[0];
    const float* prev    = (const float*)d_in[1];
    const float* mask    = (const float*)d_in[2];
    const float* wq_lin  = (const float*)d_in[3];
    const float* wq_conv = (const float*)d_in[4];
    const float* bq      = (const float*)d_in[5];
    const float* wk_lin  = (const float*)d_in[6];
    const float* wk_conv = (const float*)d_in[7];
    const float* bk      = (const float*)d_in[8];
    const float* wv_lin  = (const float*)d_in[9];
    const float* wv_conv = (const float*)d_in[10];
    const float* bv      = (const float*)d_in[11];
    const float* wo_lin  = (const float*)d_in[12];

    float* out = (float*)d_out;            // [2,4,512,1024]
    float* qk  = out + BCFWv;              // [2,4,8,1024,1024]

    float* glin = nullptr;
    bf16 *whi = nullptr, *wlo = nullptr, *xhi = nullptr, *xlo = nullptr;
    bf16 *ahi = nullptr, *alo = nullptr;
    cudaGetSymbolAddress((void**)&glin, g_lin);
    cudaGetSymbolAddress((void**)&whi, g_whi);
    cudaGetSymbolAddress((void**)&wlo, g_wlo);
    cudaGetSymbolAddress((void**)&xhi, g_xt_hi);
    cudaGetSymbolAddress((void**)&xlo, g_xt_lo);
    cudaGetSymbolAddress((void**)&ahi, g_at_hi);
    cudaGetSymbolAddress((void**)&alo, g_at_lo);

    const size_t WSZ = (size_t)Cv * Fv * Fv;   // 1M per weight set

    // 0) conversions
    cvt_weights<<<(4 * 1048576) / 256, 256>>>(wq_lin, wk_lin, wv_lin, wo_lin);
    transpose_x<<<dim3(Wv / 32, Fv / 32, BCv), 256>>>(x);

    // 1) q/k/v projections in ONE launch (z = set*8 + bc)
    mc_gemm_mma<<<dim3(Wv / 128, Fv / 128, 3 * BCv), 256>>>(whi, wlo, xhi, xlo, glin);

    // 2) conv + bias + rotary -> bf16 q,k,v
    const int conv_threads = 3 * Bv * (Fv / 2) * Wv;
    conv_rot<<<conv_threads / 256, 256>>>(wq_conv, bq, wk_conv, bk, wv_conv, bv);

    // 3+4) fused scores + softmax + P@V
    attn_fused<<<dim3(Wv / 128, BCv * Hv), 256>>>(prev, mask, qk);

    // 5) output projection
    mc_gemm_mma<<<dim3(Wv / 128, Fv / 128, BCv), 256>>>(whi + 3 * WSZ, wlo + 3 * WSZ,
                                                        ahi, alo, out);
}